// round 4
// baseline (speedup 1.0000x reference)
#include <cuda_runtime.h>
#include <mma.h>
#include <cstdint>

using namespace nvcuda;

// ---------------------------------------------------------------------------
// Stochastic_encoder (VGAE GCN encoder).
//   CSR(dst) built once, reused for all 3 aggregations.
//   GEMMs: 3xTF32-split wmma tensor-core (error ~2^-22, fp32-class accuracy).
//   ts = A@W (raw);  aggregation applies dinv weights:
//     out[d] = dinv[d]*( dinv[d]*ts[d] + sum_s dinv[s]*ts[s] ) + b
// ---------------------------------------------------------------------------

#define NMAX   50176
#define EMAX   800000
#define HDIM   128
#define SCAN_B 1024

__device__ int   g_deg   [NMAX];
__device__ int   g_base  [NMAX];
__device__ int   g_cursor[NMAX];
__device__ int   g_part  [256];
__device__ int   g_adj   [EMAX];
__device__ float g_dinv  [NMAX];
__device__ float g_ts1   [(size_t)NMAX * HDIM];
__device__ float g_h     [(size_t)NMAX * HDIM];
__device__ float g_ts2   [(size_t)NMAX * 2 * HDIM];

// ---------------------------------------------------------------------------

__global__ void k_zero_int(int* __restrict__ p, int n) {
    int i = blockIdx.x * blockDim.x + threadIdx.x;
    if (i < n) p[i] = 0;
}

__global__ void k_count(const int* __restrict__ dst, int* __restrict__ deg, int E) {
    int i = blockIdx.x * blockDim.x + threadIdx.x;
    if (i < E) atomicAdd(&deg[dst[i]], 1);
}

__global__ void k_dinv(const int* __restrict__ deg, float* __restrict__ dinv, int n) {
    int i = blockIdx.x * blockDim.x + threadIdx.x;
    if (i < n) dinv[i] = rsqrtf((float)deg[i] + 1.0f);
}

// --- 3-kernel exclusive scan of deg -> base (cursor = base copy) ----------
__global__ void k_scan_block(const int* __restrict__ deg, int* __restrict__ base,
                             int* __restrict__ part, int n)
{
    __shared__ int sh[SCAN_B];
    int gi = blockIdx.x * SCAN_B + threadIdx.x;
    int v = (gi < n) ? deg[gi] : 0;
    sh[threadIdx.x] = v;
    __syncthreads();
    #pragma unroll
    for (int off = 1; off < SCAN_B; off <<= 1) {
        int t = (threadIdx.x >= off) ? sh[threadIdx.x - off] : 0;
        __syncthreads();
        sh[threadIdx.x] += t;
        __syncthreads();
    }
    if (gi < n) base[gi] = sh[threadIdx.x] - v;   // exclusive
    if (threadIdx.x == SCAN_B - 1) part[blockIdx.x] = sh[threadIdx.x];
}

__global__ void k_scan_part(int* __restrict__ part, int nb) {
    if (threadIdx.x == 0) {
        int acc = 0;
        for (int i = 0; i < nb; i++) { int v = part[i]; part[i] = acc; acc += v; }
    }
}

__global__ void k_scan_add(int* __restrict__ base, int* __restrict__ cursor,
                           const int* __restrict__ part, int n) {
    int gi = blockIdx.x * SCAN_B + threadIdx.x;
    if (gi < n) {
        int b = base[gi] + part[blockIdx.x];
        base[gi]   = b;
        cursor[gi] = b;   // fill kernel bumps cursor directly
    }
}

__global__ void k_fill(const int* __restrict__ src, const int* __restrict__ dst,
                       int* __restrict__ cursor, int* __restrict__ adj, int E)
{
    int i = blockIdx.x * blockDim.x + threadIdx.x;
    if (i < E) {
        int pos = atomicAdd(&cursor[dst[i]], 1);
        adj[pos] = src[i];
    }
}

// ---------------------------------------------------------------------------
// 3xTF32-split tensor-core GEMM:
//   ts[r, blockIdx.y*128 + c] = (A[N,K] @ Wsel[K,128])[r,c]
// Wsel = (blockIdx.y ? Wb : Wa). BM=128, BN=128, BK=16, 8 warps (4x2).
// Split a = hi + lo per tile element; accumulate hi*hi + lo*hi + hi*lo.
// Rows >= N produce garbage in scratch (ts sized NMAX rows), never read.
// ---------------------------------------------------------------------------
#define BM 128
#define BN 128
#define BK 16

__global__ __launch_bounds__(256, 2)
void k_gemm_tf32(const float* __restrict__ A,
                 const float* __restrict__ Wa, const float* __restrict__ Wb,
                 float* __restrict__ ts, int N, int K, int ldts)
{
    __shared__ float As_hi[BM][BK];
    __shared__ float As_lo[BM][BK];
    __shared__ float Bs_hi[BK][BN];
    __shared__ float Bs_lo[BK][BN];

    const float* W = blockIdx.y ? Wb : Wa;
    const int coloff = blockIdx.y * 128;

    const int tid  = threadIdx.x;
    const int wid  = tid >> 5;
    const int wm   = wid >> 1;        // 0..3  (32-row stripes)
    const int wn   = wid & 1;         // 0..1  (64-col stripes)
    const int row0 = blockIdx.x * BM;

    wmma::fragment<wmma::accumulator, 16, 16, 8, float> c[2][4];
    #pragma unroll
    for (int mi = 0; mi < 2; mi++)
        #pragma unroll
        for (int ni = 0; ni < 4; ni++)
            wmma::fill_fragment(c[mi][ni], 0.0f);

    for (int k0 = 0; k0 < K; k0 += BK) {
        // --- A tile: 128x16, 2 float4 per thread ---
        {
            const int r  = tid >> 1;            // 0..127
            const int c4 = (tid & 1) * 2;       // 0 or 2 (float4 index in 4)
            const float* ap = A + (size_t)(row0 + r) * K + k0;
            #pragma unroll
            for (int p = 0; p < 2; p++) {
                float4 v = make_float4(0.f, 0.f, 0.f, 0.f);
                if (row0 + r < N) v = *(const float4*)(ap + (c4 + p) * 4);
                float* hi = &As_hi[r][(c4 + p) * 4];
                float* lo = &As_lo[r][(c4 + p) * 4];
                float hx = wmma::__float_to_tf32(v.x);
                float hy = wmma::__float_to_tf32(v.y);
                float hz = wmma::__float_to_tf32(v.z);
                float hw = wmma::__float_to_tf32(v.w);
                hi[0] = hx; hi[1] = hy; hi[2] = hz; hi[3] = hw;
                lo[0] = wmma::__float_to_tf32(v.x - hx);
                lo[1] = wmma::__float_to_tf32(v.y - hy);
                lo[2] = wmma::__float_to_tf32(v.z - hz);
                lo[3] = wmma::__float_to_tf32(v.w - hw);
            }
        }
        // --- W tile: 16x128, 2 float4 per thread ---
        {
            #pragma unroll
            for (int p = 0; p < 2; p++) {
                int idx = tid * 2 + p;          // 0..511 float4s
                int r   = idx >> 5;             // 0..15
                int cc  = (idx & 31) * 4;       // 0..124
                float4 v = *(const float4*)(W + (size_t)(k0 + r) * 128 + cc);
                float hx = wmma::__float_to_tf32(v.x);
                float hy = wmma::__float_to_tf32(v.y);
                float hz = wmma::__float_to_tf32(v.z);
                float hw = wmma::__float_to_tf32(v.w);
                float* hi = &Bs_hi[r][cc];
                float* lo = &Bs_lo[r][cc];
                hi[0] = hx; hi[1] = hy; hi[2] = hz; hi[3] = hw;
                lo[0] = wmma::__float_to_tf32(v.x - hx);
                lo[1] = wmma::__float_to_tf32(v.y - hy);
                lo[2] = wmma::__float_to_tf32(v.z - hz);
                lo[3] = wmma::__float_to_tf32(v.w - hw);
            }
        }
        __syncthreads();

        #pragma unroll
        for (int kk = 0; kk < BK; kk += 8) {
            wmma::fragment<wmma::matrix_a, 16, 16, 8, wmma::precision::tf32,
                           wmma::row_major> ah[2], al[2];
            #pragma unroll
            for (int mi = 0; mi < 2; mi++) {
                wmma::load_matrix_sync(ah[mi], &As_hi[wm * 32 + mi * 16][kk], BK);
                wmma::load_matrix_sync(al[mi], &As_lo[wm * 32 + mi * 16][kk], BK);
            }
            #pragma unroll
            for (int ni = 0; ni < 4; ni++) {
                wmma::fragment<wmma::matrix_b, 16, 16, 8, wmma::precision::tf32,
                               wmma::row_major> bh, bl;
                wmma::load_matrix_sync(bh, &Bs_hi[kk][wn * 64 + ni * 16], BN);
                wmma::load_matrix_sync(bl, &Bs_lo[kk][wn * 64 + ni * 16], BN);
                #pragma unroll
                for (int mi = 0; mi < 2; mi++) {
                    wmma::mma_sync(c[mi][ni], ah[mi], bh, c[mi][ni]);
                    wmma::mma_sync(c[mi][ni], al[mi], bh, c[mi][ni]);
                    wmma::mma_sync(c[mi][ni], ah[mi], bl, c[mi][ni]);
                }
            }
        }
        __syncthreads();
    }

    #pragma unroll
    for (int mi = 0; mi < 2; mi++)
        #pragma unroll
        for (int ni = 0; ni < 4; ni++) {
            float* p = ts + (size_t)(row0 + wm * 32 + mi * 16) * ldts
                          + coloff + wn * 64 + ni * 16;
            wmma::store_matrix_sync(p, c[mi][ni], ldts, wmma::mem_row_major);
        }
}

// ---------------------------------------------------------------------------
// Gather-aggregation, 128 wide (layer 1): warp per node.
//   h[d] = relu( dinv[d]*( dinv[d]*ts[d] + sum_s dinv[s]*ts[s] ) + b )
// ---------------------------------------------------------------------------
__global__ __launch_bounds__(256)
void k_agg128(const float* __restrict__ ts, const int* __restrict__ adj,
              const int* __restrict__ base, const int* __restrict__ deg,
              const float* __restrict__ dinv, const float* __restrict__ b,
              float* __restrict__ h, int N)
{
    int node = (blockIdx.x * blockDim.x + threadIdx.x) >> 5;
    int lane = threadIdx.x & 31;
    if (node >= N) return;

    float di = __ldg(&dinv[node]);
    float4 sv = __ldg((const float4*)(ts + (size_t)node * 128) + lane);
    float4 acc;
    acc.x = sv.x * di; acc.y = sv.y * di; acc.z = sv.z * di; acc.w = sv.w * di;

    int e0 = base[node], cnt = deg[node];
    for (int eb = 0; eb < cnt; eb += 32) {
        int rem = cnt - eb;
        int myidx = (lane < rem) ? __ldg(&adj[e0 + eb + lane]) : 0;
        int m = rem < 32 ? rem : 32;
        for (int j = 0; j < m; j++) {
            int s = __shfl_sync(0xffffffffu, myidx, j);
            float w = __ldg(&dinv[s]);
            float4 v = __ldg((const float4*)(ts + (size_t)s * 128) + lane);
            acc.x = fmaf(v.x, w, acc.x); acc.y = fmaf(v.y, w, acc.y);
            acc.z = fmaf(v.z, w, acc.z); acc.w = fmaf(v.w, w, acc.w);
        }
    }

    float4 bb = __ldg((const float4*)b + lane);
    float4 o;
    o.x = fmaxf(fmaf(acc.x, di, bb.x), 0.f);
    o.y = fmaxf(fmaf(acc.y, di, bb.y), 0.f);
    o.z = fmaxf(fmaf(acc.z, di, bb.z), 0.f);
    o.w = fmaxf(fmaf(acc.w, di, bb.w), 0.f);
    ((float4*)(h + (size_t)node * 128))[lane] = o;
}

// ---------------------------------------------------------------------------
// Gather-aggregation, 256 wide (mu || logstd): warp per node, 8 floats/lane.
// ---------------------------------------------------------------------------
__global__ __launch_bounds__(256)
void k_agg256(const float* __restrict__ ts2, const int* __restrict__ adj,
              const int* __restrict__ base, const int* __restrict__ deg,
              const float* __restrict__ dinv,
              const float* __restrict__ bmu, const float* __restrict__ bls,
              float* __restrict__ mu, float* __restrict__ ls, int N)
{
    int node = (blockIdx.x * blockDim.x + threadIdx.x) >> 5;
    int lane = threadIdx.x & 31;
    if (node >= N) return;

    float di = __ldg(&dinv[node]);
    const float4* self = (const float4*)(ts2 + (size_t)node * 256);
    float4 svm = __ldg(self + lane);
    float4 svl = __ldg(self + 32 + lane);
    float4 am, al;
    am.x = svm.x * di; am.y = svm.y * di; am.z = svm.z * di; am.w = svm.w * di;
    al.x = svl.x * di; al.y = svl.y * di; al.z = svl.z * di; al.w = svl.w * di;

    int e0 = base[node], cnt = deg[node];
    for (int eb = 0; eb < cnt; eb += 32) {
        int rem = cnt - eb;
        int myidx = (lane < rem) ? __ldg(&adj[e0 + eb + lane]) : 0;
        int m = rem < 32 ? rem : 32;
        for (int j = 0; j < m; j++) {
            int s = __shfl_sync(0xffffffffu, myidx, j);
            float w = __ldg(&dinv[s]);
            const float4* row = (const float4*)(ts2 + (size_t)s * 256);
            float4 vm = __ldg(row + lane);
            float4 vl = __ldg(row + 32 + lane);
            am.x = fmaf(vm.x, w, am.x); am.y = fmaf(vm.y, w, am.y);
            am.z = fmaf(vm.z, w, am.z); am.w = fmaf(vm.w, w, am.w);
            al.x = fmaf(vl.x, w, al.x); al.y = fmaf(vl.y, w, al.y);
            al.z = fmaf(vl.z, w, al.z); al.w = fmaf(vl.w, w, al.w);
        }
    }

    float4 bm = __ldg((const float4*)bmu + lane);
    float4 bl = __ldg((const float4*)bls + lane);
    float4 om, ol;
    om.x = fmaf(am.x, di, bm.x); om.y = fmaf(am.y, di, bm.y);
    om.z = fmaf(am.z, di, bm.z); om.w = fmaf(am.w, di, bm.w);
    ol.x = fmaf(al.x, di, bl.x); ol.y = fmaf(al.y, di, bl.y);
    ol.z = fmaf(al.z, di, bl.z); ol.w = fmaf(al.w, di, bl.w);
    ((float4*)(mu + (size_t)node * 128))[lane] = om;
    ((float4*)(ls + (size_t)node * 128))[lane] = ol;
}

// ---------------------------------------------------------------------------

extern "C" void kernel_launch(void* const* d_in, const int* in_sizes, int n_in,
                              void* d_out, int out_size)
{
    const float* x   = (const float*)d_in[0];
    const int*   ei  = (const int*)  d_in[1];
    const float* W1  = (const float*)d_in[2];
    const float* b1  = (const float*)d_in[3];
    const float* Wmu = (const float*)d_in[4];
    const float* bmu = (const float*)d_in[5];
    const float* Wls = (const float*)d_in[6];
    const float* bls = (const float*)d_in[7];

    const int N = in_sizes[0] / 256;   // C_in = 256
    const int E = in_sizes[1] / 2;
    const int* src = ei;
    const int* dst = ei + E;

    float* out = (float*)d_out;
    float* mu  = out;
    float* ls  = out + (size_t)N * HDIM;

    int *deg, *base, *cursor, *part, *adj;
    float *dinv, *ts1, *h, *ts2;
    cudaGetSymbolAddress((void**)&deg,    g_deg);
    cudaGetSymbolAddress((void**)&base,   g_base);
    cudaGetSymbolAddress((void**)&cursor, g_cursor);
    cudaGetSymbolAddress((void**)&part,   g_part);
    cudaGetSymbolAddress((void**)&adj,    g_adj);
    cudaGetSymbolAddress((void**)&dinv,   g_dinv);
    cudaGetSymbolAddress((void**)&ts1,    g_ts1);
    cudaGetSymbolAddress((void**)&h,      g_h);
    cudaGetSymbolAddress((void**)&ts2,    g_ts2);

    const int nb   = (N + 255) / 256;
    const int eb   = (E + 255) / 256;
    const int gb   = (N + BM - 1) / BM;
    const int sbnk = (N + SCAN_B - 1) / SCAN_B;
    const int ab   = (N * 32 + 255) / 256;   // warp per node

    // degree + dinv + CSR (reused by all 3 aggregations)
    k_zero_int<<<nb, 256>>>(deg, N);
    k_count   <<<eb, 256>>>(dst, deg, E);
    k_dinv    <<<nb, 256>>>(deg, dinv, N);
    k_scan_block<<<sbnk, SCAN_B>>>(deg, base, part, N);
    k_scan_part <<<1, 32>>>(part, sbnk);
    k_scan_add  <<<sbnk, SCAN_B>>>(base, cursor, part, N);
    k_fill      <<<eb, 256>>>(src, dst, cursor, adj, E);

    // layer 1
    k_gemm_tf32<<<dim3(gb, 1), 256>>>(x, W1, W1, ts1, N, 256, 128);
    k_agg128   <<<ab, 256>>>(ts1, adj, base, deg, dinv, b1, h, N);

    // layer 2: both heads in one launch (grid.y selects Wmu/Wls -> ts2 halves)
    k_gemm_tf32<<<dim3(gb, 2), 256>>>(h, Wmu, Wls, ts2, N, 128, 256);
    k_agg256   <<<ab, 256>>>(ts2, adj, base, deg, dinv, bmu, bls, mu, ls, N);
}

// round 5
// speedup vs baseline: 1.9927x; 1.9927x over previous
#include <cuda_runtime.h>
#include <cstdint>

// ---------------------------------------------------------------------------
// Stochastic_encoder (VGAE GCN encoder), fp32, CSR gather-aggregation,
// double-buffered SGEMM.
//   CSR(dst) built once, reused for all 3 aggregations.
//   ts = (A@W)*dinv[row]
//   out[d] = dinv[d]*( ts[d] + sum_{s in adj(d)} ts[s] ) + b   (gather)
// ---------------------------------------------------------------------------

#define NMAX   50176
#define EMAX   800000
#define HDIM   128
#define SCAN_B 1024
#define BK     16

__device__ int   g_deg   [NMAX];
__device__ int   g_base  [NMAX];
__device__ int   g_cursor[NMAX];
__device__ int   g_part  [256];
__device__ int   g_adj   [EMAX];
__device__ float g_dinv  [NMAX];
__device__ float g_ts1   [(size_t)NMAX * HDIM];
__device__ float g_h     [(size_t)NMAX * HDIM];
__device__ float g_ts2   [(size_t)NMAX * 2 * HDIM];

// ---------------------------------------------------------------------------

__global__ void k_zero_int(int* __restrict__ p, int n) {
    int i = blockIdx.x * blockDim.x + threadIdx.x;
    if (i < n) p[i] = 0;
}

__global__ void k_count(const int* __restrict__ dst, int* __restrict__ deg, int E) {
    int i = blockIdx.x * blockDim.x + threadIdx.x;
    if (i < E) atomicAdd(&deg[dst[i]], 1);
}

__global__ void k_dinv(const int* __restrict__ deg, float* __restrict__ dinv, int n) {
    int i = blockIdx.x * blockDim.x + threadIdx.x;
    if (i < n) dinv[i] = rsqrtf((float)deg[i] + 1.0f);
}

// --- 3-kernel exclusive scan of deg -> base (cursor = base copy) ----------
__global__ void k_scan_block(const int* __restrict__ deg, int* __restrict__ base,
                             int* __restrict__ part, int n)
{
    __shared__ int sh[SCAN_B];
    int gi = blockIdx.x * SCAN_B + threadIdx.x;
    int v = (gi < n) ? deg[gi] : 0;
    sh[threadIdx.x] = v;
    __syncthreads();
    #pragma unroll
    for (int off = 1; off < SCAN_B; off <<= 1) {
        int t = (threadIdx.x >= off) ? sh[threadIdx.x - off] : 0;
        __syncthreads();
        sh[threadIdx.x] += t;
        __syncthreads();
    }
    if (gi < n) base[gi] = sh[threadIdx.x] - v;   // exclusive
    if (threadIdx.x == SCAN_B - 1) part[blockIdx.x] = sh[threadIdx.x];
}

__global__ void k_scan_part(int* __restrict__ part, int nb) {
    if (threadIdx.x == 0) {
        int acc = 0;
        for (int i = 0; i < nb; i++) { int v = part[i]; part[i] = acc; acc += v; }
    }
}

__global__ void k_scan_add(int* __restrict__ base, int* __restrict__ cursor,
                           const int* __restrict__ part, int n) {
    int gi = blockIdx.x * SCAN_B + threadIdx.x;
    if (gi < n) {
        int b = base[gi] + part[blockIdx.x];
        base[gi]   = b;
        cursor[gi] = b;
    }
}

__global__ void k_fill(const int* __restrict__ src, const int* __restrict__ dst,
                       int* __restrict__ cursor, int* __restrict__ adj, int E)
{
    int i = blockIdx.x * blockDim.x + threadIdx.x;
    if (i < E) {
        int pos = atomicAdd(&cursor[dst[i]], 1);
        adj[pos] = src[i];
    }
}

// ---------------------------------------------------------------------------
// Double-buffered SGEMM:
//   ts[r, blockIdx.y*128 + c] = (A[N,K] @ Wsel[K,128])[r,c] * dinv[r]
// Wsel = (blockIdx.y ? Wb : Wa). BM=128, BN=128, BK=16, 256 thr, 8x8 micro.
// Global prefetch of tile t+1 overlaps compute of tile t; one sync/iter.
// ---------------------------------------------------------------------------
__global__ __launch_bounds__(256, 2)
void k_gemm128(const float* __restrict__ A,
               const float* __restrict__ Wa, const float* __restrict__ Wb,
               const float* __restrict__ dinv, float* __restrict__ ts,
               int N, int K, int ldts)
{
    __shared__ float As[2][BK][132];   // [k][m], 132 pad -> 16B-aligned rows
    __shared__ float Bs[2][BK][128];

    const float* W = blockIdx.y ? Wb : Wa;
    const int coloff = blockIdx.y * 128;

    const int tid  = threadIdx.x;
    const int tx   = tid & 15;
    const int ty   = tid >> 4;
    const int row0 = blockIdx.x * 128;

    // loader indices
    const int ac = tid & 3;          // float4 index within BK=16 k-cols
    const int am = tid >> 2;         // row 0..63 (2 passes -> 128)
    const int br = tid >> 4;         // k-row 0..15
    const int bc = (tid & 15) * 8;   // col 0..120

    float acc[8][8];
    #pragma unroll
    for (int i = 0; i < 8; i++)
        #pragma unroll
        for (int j = 0; j < 8; j++) acc[i][j] = 0.0f;

    const int T = K >> 4;
    float4 va[2], vb[2];

    // prefetch tile 0
    #pragma unroll
    for (int p = 0; p < 2; p++) {
        int r = row0 + am + 64 * p;
        va[p] = (r < N) ? *(const float4*)(A + (size_t)r * K + ac * 4)
                        : make_float4(0.f, 0.f, 0.f, 0.f);
    }
    vb[0] = *(const float4*)(W + (size_t)br * 128 + bc);
    vb[1] = *(const float4*)(W + (size_t)br * 128 + bc + 4);

    // store tile 0 into buf 0
    #pragma unroll
    for (int p = 0; p < 2; p++) {
        int m = am + 64 * p;
        As[0][ac * 4 + 0][m] = va[p].x;
        As[0][ac * 4 + 1][m] = va[p].y;
        As[0][ac * 4 + 2][m] = va[p].z;
        As[0][ac * 4 + 3][m] = va[p].w;
    }
    *(float4*)&Bs[0][br][bc]     = vb[0];
    *(float4*)&Bs[0][br][bc + 4] = vb[1];
    __syncthreads();

    int buf = 0;
    for (int t = 0; t < T; t++) {
        // prefetch tile t+1 (global -> regs), overlapped with compute below
        if (t + 1 < T) {
            int k0 = (t + 1) << 4;
            #pragma unroll
            for (int p = 0; p < 2; p++) {
                int r = row0 + am + 64 * p;
                va[p] = (r < N) ? *(const float4*)(A + (size_t)r * K + k0 + ac * 4)
                                : make_float4(0.f, 0.f, 0.f, 0.f);
            }
            vb[0] = *(const float4*)(W + (size_t)(k0 + br) * 128 + bc);
            vb[1] = *(const float4*)(W + (size_t)(k0 + br) * 128 + bc + 4);
        }

        // compute on buf
        #pragma unroll
        for (int kk = 0; kk < BK; kk++) {
            float a[8], b[8];
            float4 a0 = *(float4*)&As[buf][kk][ty * 8];
            float4 a1 = *(float4*)&As[buf][kk][ty * 8 + 4];
            a[0] = a0.x; a[1] = a0.y; a[2] = a0.z; a[3] = a0.w;
            a[4] = a1.x; a[5] = a1.y; a[6] = a1.z; a[7] = a1.w;
            float4 b0 = *(float4*)&Bs[buf][kk][tx * 8];
            float4 b1 = *(float4*)&Bs[buf][kk][tx * 8 + 4];
            b[0] = b0.x; b[1] = b0.y; b[2] = b0.z; b[3] = b0.w;
            b[4] = b1.x; b[5] = b1.y; b[6] = b1.z; b[7] = b1.w;
            #pragma unroll
            for (int i = 0; i < 8; i++)
                #pragma unroll
                for (int j = 0; j < 8; j++)
                    acc[i][j] = fmaf(a[i], b[j], acc[i][j]);
        }

        // store tile t+1 into the other buffer
        if (t + 1 < T) {
            int nb_ = buf ^ 1;
            #pragma unroll
            for (int p = 0; p < 2; p++) {
                int m = am + 64 * p;
                As[nb_][ac * 4 + 0][m] = va[p].x;
                As[nb_][ac * 4 + 1][m] = va[p].y;
                As[nb_][ac * 4 + 2][m] = va[p].z;
                As[nb_][ac * 4 + 3][m] = va[p].w;
            }
            *(float4*)&Bs[nb_][br][bc]     = vb[0];
            *(float4*)&Bs[nb_][br][bc + 4] = vb[1];
            __syncthreads();
            buf = nb_;
        }
    }

    // epilogue: scale by dinv[row], write float4s
    #pragma unroll
    for (int i = 0; i < 8; i++) {
        int r = row0 + ty * 8 + i;
        if (r < N) {
            float di = dinv[r];
            float* dst = ts + (size_t)r * ldts + coloff + tx * 8;
            float4 o0, o1;
            o0.x = acc[i][0] * di; o0.y = acc[i][1] * di;
            o0.z = acc[i][2] * di; o0.w = acc[i][3] * di;
            o1.x = acc[i][4] * di; o1.y = acc[i][5] * di;
            o1.z = acc[i][6] * di; o1.w = acc[i][7] * di;
            *(float4*)dst       = o0;
            *(float4*)(dst + 4) = o1;
        }
    }
}

// ---------------------------------------------------------------------------
// Gather-aggregation, 128 wide (layer 1): warp per node.
//   h[d] = relu( dinv[d]*(ts[d] + sum_{s in adj(d)} ts[s]) + b )
// ---------------------------------------------------------------------------
__global__ __launch_bounds__(256)
void k_agg128(const float* __restrict__ ts, const int* __restrict__ adj,
              const int* __restrict__ base, const int* __restrict__ deg,
              const float* __restrict__ dinv, const float* __restrict__ b,
              float* __restrict__ h, int N)
{
    int node = (blockIdx.x * blockDim.x + threadIdx.x) >> 5;
    int lane = threadIdx.x & 31;
    if (node >= N) return;

    float4 acc = __ldg((const float4*)(ts + (size_t)node * 128) + lane);  // self
    int e0 = base[node], cnt = deg[node];

    for (int eb = 0; eb < cnt; eb += 32) {
        int rem = cnt - eb;
        int myidx = (lane < rem) ? __ldg(&adj[e0 + eb + lane]) : 0;
        int m = rem < 32 ? rem : 32;
        for (int j = 0; j < m; j++) {
            int s = __shfl_sync(0xffffffffu, myidx, j);
            float4 v = __ldg((const float4*)(ts + (size_t)s * 128) + lane);
            acc.x += v.x; acc.y += v.y; acc.z += v.z; acc.w += v.w;
        }
    }

    float di = dinv[node];
    float4 bb = __ldg((const float4*)b + lane);
    float4 o;
    o.x = fmaxf(fmaf(acc.x, di, bb.x), 0.f);
    o.y = fmaxf(fmaf(acc.y, di, bb.y), 0.f);
    o.z = fmaxf(fmaf(acc.z, di, bb.z), 0.f);
    o.w = fmaxf(fmaf(acc.w, di, bb.w), 0.f);
    ((float4*)(h + (size_t)node * 128))[lane] = o;
}

// ---------------------------------------------------------------------------
// Gather-aggregation, 256 wide (mu || logstd): warp per node, 8 floats/lane.
// ---------------------------------------------------------------------------
__global__ __launch_bounds__(256)
void k_agg256(const float* __restrict__ ts2, const int* __restrict__ adj,
              const int* __restrict__ base, const int* __restrict__ deg,
              const float* __restrict__ dinv,
              const float* __restrict__ bmu, const float* __restrict__ bls,
              float* __restrict__ mu, float* __restrict__ ls, int N)
{
    int node = (blockIdx.x * blockDim.x + threadIdx.x) >> 5;
    int lane = threadIdx.x & 31;
    if (node >= N) return;

    const float4* self = (const float4*)(ts2 + (size_t)node * 256);
    float4 am = __ldg(self + lane);        // mu cols
    float4 al = __ldg(self + 32 + lane);   // ls cols
    int e0 = base[node], cnt = deg[node];

    for (int eb = 0; eb < cnt; eb += 32) {
        int rem = cnt - eb;
        int myidx = (lane < rem) ? __ldg(&adj[e0 + eb + lane]) : 0;
        int m = rem < 32 ? rem : 32;
        for (int j = 0; j < m; j++) {
            int s = __shfl_sync(0xffffffffu, myidx, j);
            const float4* row = (const float4*)(ts2 + (size_t)s * 256);
            float4 vm = __ldg(row + lane);
            float4 vl = __ldg(row + 32 + lane);
            am.x += vm.x; am.y += vm.y; am.z += vm.z; am.w += vm.w;
            al.x += vl.x; al.y += vl.y; al.z += vl.z; al.w += vl.w;
        }
    }

    float di = dinv[node];
    float4 bm = __ldg((const float4*)bmu + lane);
    float4 bl = __ldg((const float4*)bls + lane);
    float4 om, ol;
    om.x = fmaf(am.x, di, bm.x); om.y = fmaf(am.y, di, bm.y);
    om.z = fmaf(am.z, di, bm.z); om.w = fmaf(am.w, di, bm.w);
    ol.x = fmaf(al.x, di, bl.x); ol.y = fmaf(al.y, di, bl.y);
    ol.z = fmaf(al.z, di, bl.z); ol.w = fmaf(al.w, di, bl.w);
    ((float4*)(mu + (size_t)node * 128))[lane] = om;
    ((float4*)(ls + (size_t)node * 128))[lane] = ol;
}

// ---------------------------------------------------------------------------

extern "C" void kernel_launch(void* const* d_in, const int* in_sizes, int n_in,
                              void* d_out, int out_size)
{
    const float* x   = (const float*)d_in[0];
    const int*   ei  = (const int*)  d_in[1];
    const float* W1  = (const float*)d_in[2];
    const float* b1  = (const float*)d_in[3];
    const float* Wmu = (const float*)d_in[4];
    const float* bmu = (const float*)d_in[5];
    const float* Wls = (const float*)d_in[6];
    const float* bls = (const float*)d_in[7];

    const int N = in_sizes[0] / 256;   // C_in = 256
    const int E = in_sizes[1] / 2;
    const int* src = ei;
    const int* dst = ei + E;

    float* out = (float*)d_out;
    float* mu  = out;
    float* ls  = out + (size_t)N * HDIM;

    int *deg, *base, *cursor, *part, *adj;
    float *dinv, *ts1, *h, *ts2;
    cudaGetSymbolAddress((void**)&deg,    g_deg);
    cudaGetSymbolAddress((void**)&base,   g_base);
    cudaGetSymbolAddress((void**)&cursor, g_cursor);
    cudaGetSymbolAddress((void**)&part,   g_part);
    cudaGetSymbolAddress((void**)&adj,    g_adj);
    cudaGetSymbolAddress((void**)&dinv,   g_dinv);
    cudaGetSymbolAddress((void**)&ts1,    g_ts1);
    cudaGetSymbolAddress((void**)&h,      g_h);
    cudaGetSymbolAddress((void**)&ts2,    g_ts2);

    const int nb   = (N + 255) / 256;
    const int eb   = (E + 255) / 256;
    const int gb   = (N + 127) / 128;
    const int sbnk = (N + SCAN_B - 1) / SCAN_B;
    const int ab   = (N * 32 + 255) / 256;   // warp per node

    // degree + dinv + CSR (reused by all 3 aggregations)
    k_zero_int<<<nb, 256>>>(deg, N);
    k_count   <<<eb, 256>>>(dst, deg, E);
    k_dinv    <<<nb, 256>>>(deg, dinv, N);
    k_scan_block<<<sbnk, SCAN_B>>>(deg, base, part, N);
    k_scan_part <<<1, 32>>>(part, sbnk);
    k_scan_add  <<<sbnk, SCAN_B>>>(base, cursor, part, N);
    k_fill      <<<eb, 256>>>(src, dst, cursor, adj, E);

    // layer 1
    k_gemm128<<<dim3(gb, 1), 256>>>(x, W1, W1, dinv, ts1, N, 256, 128);
    k_agg128 <<<ab, 256>>>(ts1, adj, base, deg, dinv, b1, h, N);

    // layer 2: both heads in one launch (grid.y selects Wmu/Wls -> ts2 halves)
    k_gemm128<<<dim3(gb, 2), 256>>>(h, Wmu, Wls, dinv, ts2, N, 128, 256);
    k_agg256 <<<ab, 256>>>(ts2, adj, base, deg, dinv, bmu, bls, mu, ls, N);
}

// round 6
// speedup vs baseline: 2.0787x; 1.0431x over previous
#include <cuda_runtime.h>
#include <cstdint>

// ---------------------------------------------------------------------------
// Stochastic_encoder (VGAE GCN encoder), fp32, CSR gather-aggregation,
// FFMA2 (fma.rn.f32x2) packed SGEMM.
//   CSR(dst) built once, reused for all 3 aggregations.
//   ts = (A@W)*dinv[row]
//   out[d] = dinv[d]*( ts[d] + sum_{s in adj(d)} ts[s] ) + b   (gather)
// ---------------------------------------------------------------------------

#define NMAX   50176
#define EMAX   800000
#define HDIM   128
#define SCAN_B 1024

__device__ int   g_deg   [NMAX];
__device__ int   g_base  [NMAX];
__device__ int   g_cursor[NMAX];
__device__ int   g_part  [256];
__device__ int   g_adj   [EMAX];
__device__ float g_dinv  [NMAX];
__device__ float g_ts1   [(size_t)NMAX * HDIM];
__device__ float g_h     [(size_t)NMAX * HDIM];
__device__ float g_ts2   [(size_t)NMAX * 2 * HDIM];

// --- packed f32x2 helpers (sm_100+; ptxas never emits FFMA2 from C++) ------
__device__ __forceinline__ unsigned long long f2pack(float lo, float hi) {
    unsigned long long r;
    asm("mov.b64 %0, {%1, %2};" : "=l"(r) : "f"(lo), "f"(hi));
    return r;
}
__device__ __forceinline__ void ffma2(unsigned long long& d,
                                      unsigned long long a, unsigned long long b) {
    asm("fma.rn.f32x2 %0, %1, %2, %0;" : "+l"(d) : "l"(a), "l"(b));
}
__device__ __forceinline__ unsigned long long fmul2(unsigned long long a,
                                                    unsigned long long b) {
    unsigned long long r;
    asm("mul.rn.f32x2 %0, %1, %2;" : "=l"(r) : "l"(a), "l"(b));
    return r;
}

// ---------------------------------------------------------------------------

__global__ void k_zero_int(int* __restrict__ p, int n) {
    int i = blockIdx.x * blockDim.x + threadIdx.x;
    if (i < n) p[i] = 0;
}

__global__ void k_count(const int* __restrict__ dst, int* __restrict__ deg, int E) {
    int i = blockIdx.x * blockDim.x + threadIdx.x;
    if (i < E) atomicAdd(&deg[dst[i]], 1);
}

__global__ void k_dinv(const int* __restrict__ deg, float* __restrict__ dinv, int n) {
    int i = blockIdx.x * blockDim.x + threadIdx.x;
    if (i < n) dinv[i] = rsqrtf((float)deg[i] + 1.0f);
}

// --- 3-kernel exclusive scan of deg -> base (cursor = base copy) ----------
__global__ void k_scan_block(const int* __restrict__ deg, int* __restrict__ base,
                             int* __restrict__ part, int n)
{
    __shared__ int sh[SCAN_B];
    int gi = blockIdx.x * SCAN_B + threadIdx.x;
    int v = (gi < n) ? deg[gi] : 0;
    sh[threadIdx.x] = v;
    __syncthreads();
    #pragma unroll
    for (int off = 1; off < SCAN_B; off <<= 1) {
        int t = (threadIdx.x >= off) ? sh[threadIdx.x - off] : 0;
        __syncthreads();
        sh[threadIdx.x] += t;
        __syncthreads();
    }
    if (gi < n) base[gi] = sh[threadIdx.x] - v;   // exclusive
    if (threadIdx.x == SCAN_B - 1) part[blockIdx.x] = sh[threadIdx.x];
}

__global__ void k_scan_part(int* __restrict__ part, int nb) {
    if (threadIdx.x == 0) {
        int acc = 0;
        for (int i = 0; i < nb; i++) { int v = part[i]; part[i] = acc; acc += v; }
    }
}

__global__ void k_scan_add(int* __restrict__ base, int* __restrict__ cursor,
                           const int* __restrict__ part, int n) {
    int gi = blockIdx.x * SCAN_B + threadIdx.x;
    if (gi < n) {
        int b = base[gi] + part[blockIdx.x];
        base[gi]   = b;
        cursor[gi] = b;
    }
}

__global__ void k_fill(const int* __restrict__ src, const int* __restrict__ dst,
                       int* __restrict__ cursor, int* __restrict__ adj, int E)
{
    int i = blockIdx.x * blockDim.x + threadIdx.x;
    if (i < E) {
        int pos = atomicAdd(&cursor[dst[i]], 1);
        adj[pos] = src[i];
    }
}

// ---------------------------------------------------------------------------
// FFMA2 SGEMM:
//   ts[r, blockIdx.y*128 + c] = (A[N,K] @ Wsel[K,128])[r,c] * dinv[r]
// Wsel = (blockIdx.y ? Wb : Wa). BM=128, BN=128, BK=32, 256 thr.
// 8x8 micro-tile held as 8x4 packed f32x2 accumulators (pairs along cols).
// Arithmetic is exact fp32 (identical results to scalar FFMA version).
// ---------------------------------------------------------------------------
__global__ __launch_bounds__(256, 2)
void k_gemm128(const float* __restrict__ A,
               const float* __restrict__ Wa, const float* __restrict__ Wb,
               const float* __restrict__ dinv, float* __restrict__ ts,
               int N, int K, int ldts)
{
    __shared__ float As[32][129];   // [k][m], pad 129: conflict-free transposed
    __shared__ float Bs[32][128];

    const float* W = blockIdx.y ? Wb : Wa;
    const int coloff = blockIdx.y * 128;

    const int tid  = threadIdx.x;
    const int tx   = tid & 15;      // 16 col-groups (8 cols each)
    const int ty   = tid >> 4;      // 16 row-groups (8 rows each)
    const int row0 = blockIdx.x * 128;

    unsigned long long acc[8][4];
    #pragma unroll
    for (int i = 0; i < 8; i++)
        #pragma unroll
        for (int j = 0; j < 4; j++) acc[i][j] = 0ull;

    for (int k0 = 0; k0 < K; k0 += 32) {
        // --- A tile (128 x 32), transposed into As[k][m] ---
        {
            const int c  = tid & 7;     // float4 index within 32 k-cols
            const int m0 = tid >> 3;    // row 0..31
            #pragma unroll
            for (int p = 0; p < 4; p++) {
                int m = m0 + 32 * p;
                int r = row0 + m;
                float4 v = make_float4(0.f, 0.f, 0.f, 0.f);
                if (r < N)
                    v = *(const float4*)(A + (size_t)r * K + (k0 + c * 4));
                As[c * 4 + 0][m] = v.x;
                As[c * 4 + 1][m] = v.y;
                As[c * 4 + 2][m] = v.z;
                As[c * 4 + 3][m] = v.w;
            }
        }
        // --- W tile (32 x 128) ---
        {
            const int cb  = tid & 31;
            const int kr0 = tid >> 5;
            #pragma unroll
            for (int p = 0; p < 4; p++) {
                int kr = kr0 + 8 * p;
                *(float4*)&Bs[kr][cb * 4] =
                    *(const float4*)(W + (size_t)(k0 + kr) * 128 + cb * 4);
            }
        }
        __syncthreads();

        #pragma unroll
        for (int kk = 0; kk < 32; kk++) {
            // b: 4 packed pairs straight out of smem (8B loads, adjacent cols)
            const unsigned long long* bp =
                (const unsigned long long*)&Bs[kk][tx * 8];
            unsigned long long b0 = bp[0], b1 = bp[1], b2 = bp[2], b3 = bp[3];
            #pragma unroll
            for (int i = 0; i < 8; i++) {
                float ai = As[kk][ty * 8 + i];
                unsigned long long ap = f2pack(ai, ai);
                ffma2(acc[i][0], ap, b0);
                ffma2(acc[i][1], ap, b1);
                ffma2(acc[i][2], ap, b2);
                ffma2(acc[i][3], ap, b3);
            }
        }
        __syncthreads();
    }

    // epilogue: scale by dinv[row] (packed), 8B stores
    #pragma unroll
    for (int i = 0; i < 8; i++) {
        int r = row0 + ty * 8 + i;
        if (r < N) {
            float di = dinv[r];
            unsigned long long dp = f2pack(di, di);
            unsigned long long* dst =
                (unsigned long long*)(ts + (size_t)r * ldts + coloff + tx * 8);
            #pragma unroll
            for (int j = 0; j < 4; j++)
                dst[j] = fmul2(acc[i][j], dp);
        }
    }
}

// ---------------------------------------------------------------------------
// Gather-aggregation, 128 wide (layer 1): warp per node.
//   h[d] = relu( dinv[d]*(ts[d] + sum_{s in adj(d)} ts[s]) + b )
// ---------------------------------------------------------------------------
__global__ __launch_bounds__(256)
void k_agg128(const float* __restrict__ ts, const int* __restrict__ adj,
              const int* __restrict__ base, const int* __restrict__ deg,
              const float* __restrict__ dinv, const float* __restrict__ b,
              float* __restrict__ h, int N)
{
    int node = (blockIdx.x * blockDim.x + threadIdx.x) >> 5;
    int lane = threadIdx.x & 31;
    if (node >= N) return;

    float4 acc = __ldg((const float4*)(ts + (size_t)node * 128) + lane);  // self
    int e0 = base[node], cnt = deg[node];

    for (int eb = 0; eb < cnt; eb += 32) {
        int rem = cnt - eb;
        int myidx = (lane < rem) ? __ldg(&adj[e0 + eb + lane]) : 0;
        int m = rem < 32 ? rem : 32;
        for (int j = 0; j < m; j++) {
            int s = __shfl_sync(0xffffffffu, myidx, j);
            float4 v = __ldg((const float4*)(ts + (size_t)s * 128) + lane);
            acc.x += v.x; acc.y += v.y; acc.z += v.z; acc.w += v.w;
        }
    }

    float di = dinv[node];
    float4 bb = __ldg((const float4*)b + lane);
    float4 o;
    o.x = fmaxf(fmaf(acc.x, di, bb.x), 0.f);
    o.y = fmaxf(fmaf(acc.y, di, bb.y), 0.f);
    o.z = fmaxf(fmaf(acc.z, di, bb.z), 0.f);
    o.w = fmaxf(fmaf(acc.w, di, bb.w), 0.f);
    ((float4*)(h + (size_t)node * 128))[lane] = o;
}

// ---------------------------------------------------------------------------
// Gather-aggregation, 256 wide (mu || logstd): warp per node, 8 floats/lane.
// ---------------------------------------------------------------------------
__global__ __launch_bounds__(256)
void k_agg256(const float* __restrict__ ts2, const int* __restrict__ adj,
              const int* __restrict__ base, const int* __restrict__ deg,
              const float* __restrict__ dinv,
              const float* __restrict__ bmu, const float* __restrict__ bls,
              float* __restrict__ mu, float* __restrict__ ls, int N)
{
    int node = (blockIdx.x * blockDim.x + threadIdx.x) >> 5;
    int lane = threadIdx.x & 31;
    if (node >= N) return;

    const float4* self = (const float4*)(ts2 + (size_t)node * 256);
    float4 am = __ldg(self + lane);        // mu cols
    float4 al = __ldg(self + 32 + lane);   // ls cols
    int e0 = base[node], cnt = deg[node];

    for (int eb = 0; eb < cnt; eb += 32) {
        int rem = cnt - eb;
        int myidx = (lane < rem) ? __ldg(&adj[e0 + eb + lane]) : 0;
        int m = rem < 32 ? rem : 32;
        for (int j = 0; j < m; j++) {
            int s = __shfl_sync(0xffffffffu, myidx, j);
            const float4* row = (const float4*)(ts2 + (size_t)s * 256);
            float4 vm = __ldg(row + lane);
            float4 vl = __ldg(row + 32 + lane);
            am.x += vm.x; am.y += vm.y; am.z += vm.z; am.w += vm.w;
            al.x += vl.x; al.y += vl.y; al.z += vl.z; al.w += vl.w;
        }
    }

    float di = dinv[node];
    float4 bm = __ldg((const float4*)bmu + lane);
    float4 bl = __ldg((const float4*)bls + lane);
    float4 om, ol;
    om.x = fmaf(am.x, di, bm.x); om.y = fmaf(am.y, di, bm.y);
    om.z = fmaf(am.z, di, bm.z); om.w = fmaf(am.w, di, bm.w);
    ol.x = fmaf(al.x, di, bl.x); ol.y = fmaf(al.y, di, bl.y);
    ol.z = fmaf(al.z, di, bl.z); ol.w = fmaf(al.w, di, bl.w);
    ((float4*)(mu + (size_t)node * 128))[lane] = om;
    ((float4*)(ls + (size_t)node * 128))[lane] = ol;
}

// ---------------------------------------------------------------------------

extern "C" void kernel_launch(void* const* d_in, const int* in_sizes, int n_in,
                              void* d_out, int out_size)
{
    const float* x   = (const float*)d_in[0];
    const int*   ei  = (const int*)  d_in[1];
    const float* W1  = (const float*)d_in[2];
    const float* b1  = (const float*)d_in[3];
    const float* Wmu = (const float*)d_in[4];
    const float* bmu = (const float*)d_in[5];
    const float* Wls = (const float*)d_in[6];
    const float* bls = (const float*)d_in[7];

    const int N = in_sizes[0] / 256;   // C_in = 256
    const int E = in_sizes[1] / 2;
    const int* src = ei;
    const int* dst = ei + E;

    float* out = (float*)d_out;
    float* mu  = out;
    float* ls  = out + (size_t)N * HDIM;

    int *deg, *base, *cursor, *part, *adj;
    float *dinv, *ts1, *h, *ts2;
    cudaGetSymbolAddress((void**)&deg,    g_deg);
    cudaGetSymbolAddress((void**)&base,   g_base);
    cudaGetSymbolAddress((void**)&cursor, g_cursor);
    cudaGetSymbolAddress((void**)&part,   g_part);
    cudaGetSymbolAddress((void**)&adj,    g_adj);
    cudaGetSymbolAddress((void**)&dinv,   g_dinv);
    cudaGetSymbolAddress((void**)&ts1,    g_ts1);
    cudaGetSymbolAddress((void**)&h,      g_h);
    cudaGetSymbolAddress((void**)&ts2,    g_ts2);

    const int nb   = (N + 255) / 256;
    const int eb   = (E + 255) / 256;
    const int gb   = (N + 127) / 128;
    const int sbnk = (N + SCAN_B - 1) / SCAN_B;
    const int ab   = (N * 32 + 255) / 256;   // warp per node

    // degree + dinv + CSR (reused by all 3 aggregations)
    k_zero_int<<<nb, 256>>>(deg, N);
    k_count   <<<eb, 256>>>(dst, deg, E);
    k_dinv    <<<nb, 256>>>(deg, dinv, N);
    k_scan_block<<<sbnk, SCAN_B>>>(deg, base, part, N);
    k_scan_part <<<1, 32>>>(part, sbnk);
    k_scan_add  <<<sbnk, SCAN_B>>>(base, cursor, part, N);
    k_fill      <<<eb, 256>>>(src, dst, cursor, adj, E);

    // layer 1
    k_gemm128<<<dim3(gb, 1), 256>>>(x, W1, W1, dinv, ts1, N, 256, 128);
    k_agg128 <<<ab, 256>>>(ts1, adj, base, deg, dinv, b1, h, N);

    // layer 2: both heads in one launch (grid.y selects Wmu/Wls -> ts2 halves)
    k_gemm128<<<dim3(gb, 2), 256>>>(h, Wmu, Wls, dinv, ts2, N, 128, 256);
    k_agg256 <<<ab, 256>>>(ts2, adj, base, deg, dinv, bmu, bls, mu, ls, N);
}

// round 8
// speedup vs baseline: 2.3402x; 1.1258x over previous
#include <cuda_runtime.h>
#include <cuda_bf16.h>
#include <mma.h>
#include <cstdint>

using namespace nvcuda;

// ---------------------------------------------------------------------------
// Stochastic_encoder (VGAE GCN encoder).
//   CSR(dst) gather-aggregation (round-3 proven path, unchanged).
//   GEMMs: bf16 split-precision wmma (C = Ah*Wh + Al*Wh + Ah*Wl, fp32 accum).
//   A and W pre-split into bf16 hi/lo by streaming kernels (outside GEMM loop).
//   ts = (A@W)*dinv[row];  out[d] = dinv[d]*(ts[d] + sum ts[src]) + b
// ---------------------------------------------------------------------------

#define NMAX   50176
#define EMAX   800000
#define HDIM   128
#define SCAN_B 1024

__device__ int   g_deg   [NMAX];
__device__ int   g_base  [NMAX];
__device__ int   g_cursor[NMAX];
__device__ int   g_part  [256];
__device__ int   g_adj   [EMAX];
__device__ float g_dinv  [NMAX];
__device__ float g_ts1   [(size_t)NMAX * HDIM];
__device__ float g_h     [(size_t)NMAX * HDIM];
__device__ float g_ts2   [(size_t)NMAX * 2 * HDIM];

__device__ __nv_bfloat16 g_ah[(size_t)NMAX * 256];
__device__ __nv_bfloat16 g_al[(size_t)NMAX * 256];
__device__ __nv_bfloat16 g_wh[512 * 128];   // W1 @0 (256 rows), Wmu @256, Wls @384
__device__ __nv_bfloat16 g_wl[512 * 128];

// ---------------------------------------------------------------------------

__global__ void k_zero_int(int* __restrict__ p, int n) {
    int i = blockIdx.x * blockDim.x + threadIdx.x;
    if (i < n) p[i] = 0;
}

__global__ void k_count(const int* __restrict__ dst, int* __restrict__ deg, int E) {
    int i = blockIdx.x * blockDim.x + threadIdx.x;
    if (i < E) atomicAdd(&deg[dst[i]], 1);
}

__global__ void k_dinv(const int* __restrict__ deg, float* __restrict__ dinv, int n) {
    int i = blockIdx.x * blockDim.x + threadIdx.x;
    if (i < n) dinv[i] = rsqrtf((float)deg[i] + 1.0f);
}

// --- 3-kernel exclusive scan of deg -> base (cursor = base copy) ----------
__global__ void k_scan_block(const int* __restrict__ deg, int* __restrict__ base,
                             int* __restrict__ part, int n)
{
    __shared__ int sh[SCAN_B];
    int gi = blockIdx.x * SCAN_B + threadIdx.x;
    int v = (gi < n) ? deg[gi] : 0;
    sh[threadIdx.x] = v;
    __syncthreads();
    #pragma unroll
    for (int off = 1; off < SCAN_B; off <<= 1) {
        int t = (threadIdx.x >= off) ? sh[threadIdx.x - off] : 0;
        __syncthreads();
        sh[threadIdx.x] += t;
        __syncthreads();
    }
    if (gi < n) base[gi] = sh[threadIdx.x] - v;
    if (threadIdx.x == SCAN_B - 1) part[blockIdx.x] = sh[threadIdx.x];
}

__global__ void k_scan_part(int* __restrict__ part, int nb) {
    if (threadIdx.x == 0) {
        int acc = 0;
        for (int i = 0; i < nb; i++) { int v = part[i]; part[i] = acc; acc += v; }
    }
}

__global__ void k_scan_add(int* __restrict__ base, int* __restrict__ cursor,
                           const int* __restrict__ part, int n) {
    int gi = blockIdx.x * SCAN_B + threadIdx.x;
    if (gi < n) {
        int b = base[gi] + part[blockIdx.x];
        base[gi]   = b;
        cursor[gi] = b;
    }
}

__global__ void k_fill(const int* __restrict__ src, const int* __restrict__ dst,
                       int* __restrict__ cursor, int* __restrict__ adj, int E)
{
    int i = blockIdx.x * blockDim.x + threadIdx.x;
    if (i < E) {
        int pos = atomicAdd(&cursor[dst[i]], 1);
        adj[pos] = src[i];
    }
}

// ---------------------------------------------------------------------------
// fp32 -> bf16 (hi, lo) split: hi = bf16(v), lo = bf16(v - hi). Vectorized x4.
// ---------------------------------------------------------------------------
__global__ void k_split(const float* __restrict__ src,
                        __nv_bfloat16* __restrict__ hi,
                        __nv_bfloat16* __restrict__ lo, int n4)
{
    int i = blockIdx.x * blockDim.x + threadIdx.x;
    if (i >= n4) return;
    float4 v = ((const float4*)src)[i];
    __nv_bfloat16 hx = __float2bfloat16(v.x);
    __nv_bfloat16 hy = __float2bfloat16(v.y);
    __nv_bfloat16 hz = __float2bfloat16(v.z);
    __nv_bfloat16 hw = __float2bfloat16(v.w);
    __nv_bfloat162* hp = (__nv_bfloat162*)hi;
    __nv_bfloat162* lp = (__nv_bfloat162*)lo;
    hp[2 * i]     = __nv_bfloat162(hx, hy);
    hp[2 * i + 1] = __nv_bfloat162(hz, hw);
    lp[2 * i]     = __nv_bfloat162(__float2bfloat16(v.x - __bfloat162float(hx)),
                                   __float2bfloat16(v.y - __bfloat162float(hy)));
    lp[2 * i + 1] = __nv_bfloat162(__float2bfloat16(v.z - __bfloat162float(hz)),
                                   __float2bfloat16(v.w - __bfloat162float(hw)));
}

// ---------------------------------------------------------------------------
// bf16 split-precision wmma GEMM:
//   ts[r, blockIdx.y*128 + c] = (A[N,K] @ Wsel[K,128])[r,c] * dinv[r]
// A given as (Ah, Al) bf16 [N,K]; Wsel as (Wh,Wl) bf16 [K,128].
// BM=128, BN=128, BK=32, 8 warps (4x2), fragments m16n16k16.
// Per tile: c += Ah*Wh + Al*Wh + Ah*Wl  (fp32 accumulate).
// ---------------------------------------------------------------------------
#define A_PITCH 40    // bf16 elems per smem A row (mult of 8, dodges conflicts)
#define B_PITCH 136   // bf16 elems per smem B row

__global__ __launch_bounds__(256, 2)
void k_gemm_bf16(const __nv_bfloat16* __restrict__ Ah,
                 const __nv_bfloat16* __restrict__ Al,
                 const __nv_bfloat16* __restrict__ Wh_a,
                 const __nv_bfloat16* __restrict__ Wl_a,
                 const __nv_bfloat16* __restrict__ Wh_b,
                 const __nv_bfloat16* __restrict__ Wl_b,
                 const float* __restrict__ dinv, float* __restrict__ ts,
                 int N, int K, int ldts)
{
    // carve one aligned smem pool (A/B tiles; epilogue stage reuses it)
    __shared__ __align__(32) unsigned char smem_raw[
        128 * A_PITCH * 2 * 2 + 32 * B_PITCH * 2 * 2];
    __nv_bfloat16* Ah_s = (__nv_bfloat16*)smem_raw;                    // 128*40
    __nv_bfloat16* Al_s = Ah_s + 128 * A_PITCH;
    __nv_bfloat16* Bh_s = Al_s + 128 * A_PITCH;                        // 32*136
    __nv_bfloat16* Bl_s = Bh_s + 32 * B_PITCH;
    float*         stage = (float*)smem_raw;   // 8 warps x 16 x 20 f32 (reuse)

    const __nv_bfloat16* Wh = blockIdx.y ? Wh_b : Wh_a;
    const __nv_bfloat16* Wl = blockIdx.y ? Wl_b : Wl_a;
    const int coloff = blockIdx.y * 128;

    const int tid  = threadIdx.x;
    const int wid  = tid >> 5;
    const int lane = tid & 31;
    const int wm   = wid >> 1;        // 0..3 (32-row stripes)
    const int wn   = wid & 1;         // 0..1 (64-col stripes)
    const int row0 = blockIdx.x * 128;

    // loader indices
    const int ar  = tid >> 1;             // A row 0..127
    const int ac  = (tid & 1) * 16;       // A col 0 / 16
    const int br  = tid >> 3;             // B row 0..31
    const int bc  = (tid & 7) * 16;       // B col 0..112

    wmma::fragment<wmma::accumulator, 16, 16, 16, float> c[2][4];
    #pragma unroll
    for (int mi = 0; mi < 2; mi++)
        #pragma unroll
        for (int ni = 0; ni < 4; ni++)
            wmma::fill_fragment(c[mi][ni], 0.0f);

    for (int k0 = 0; k0 < K; k0 += 32) {
        // A tiles: 128x32 bf16 (hi & lo), 2x uint4 each per thread
        {
            const uint4* gh = (const uint4*)(Ah + (size_t)(row0 + ar) * K + k0 + ac);
            const uint4* gl = (const uint4*)(Al + (size_t)(row0 + ar) * K + k0 + ac);
            uint4* sh = (uint4*)(Ah_s + ar * A_PITCH + ac);
            uint4* sl = (uint4*)(Al_s + ar * A_PITCH + ac);
            sh[0] = gh[0]; sh[1] = gh[1];
            sl[0] = gl[0]; sl[1] = gl[1];
        }
        // B tiles: 32x128 bf16 (hi & lo)
        {
            const uint4* gh = (const uint4*)(Wh + (size_t)(k0 + br) * 128 + bc);
            const uint4* gl = (const uint4*)(Wl + (size_t)(k0 + br) * 128 + bc);
            uint4* sh = (uint4*)(Bh_s + br * B_PITCH + bc);
            uint4* sl = (uint4*)(Bl_s + br * B_PITCH + bc);
            sh[0] = gh[0]; sh[1] = gh[1];
            sl[0] = gl[0]; sl[1] = gl[1];
        }
        __syncthreads();

        #pragma unroll
        for (int kk = 0; kk < 32; kk += 16) {
            wmma::fragment<wmma::matrix_a, 16, 16, 16, __nv_bfloat16,
                           wmma::row_major> fah[2], fal[2];
            #pragma unroll
            for (int mi = 0; mi < 2; mi++) {
                wmma::load_matrix_sync(fah[mi],
                    Ah_s + (wm * 32 + mi * 16) * A_PITCH + kk, A_PITCH);
                wmma::load_matrix_sync(fal[mi],
                    Al_s + (wm * 32 + mi * 16) * A_PITCH + kk, A_PITCH);
            }
            #pragma unroll
            for (int ni = 0; ni < 4; ni++) {
                wmma::fragment<wmma::matrix_b, 16, 16, 16, __nv_bfloat16,
                               wmma::row_major> fbh, fbl;
                wmma::load_matrix_sync(fbh,
                    Bh_s + kk * B_PITCH + wn * 64 + ni * 16, B_PITCH);
                wmma::load_matrix_sync(fbl,
                    Bl_s + kk * B_PITCH + wn * 64 + ni * 16, B_PITCH);
                #pragma unroll
                for (int mi = 0; mi < 2; mi++) {
                    wmma::mma_sync(c[mi][ni], fah[mi], fbh, c[mi][ni]);
                    wmma::mma_sync(c[mi][ni], fal[mi], fbh, c[mi][ni]);
                    wmma::mma_sync(c[mi][ni], fah[mi], fbl, c[mi][ni]);
                }
            }
        }
        __syncthreads();
    }

    // epilogue: per-warp stage each 16x16 frag through smem, scale by dinv[row]
    float* my_stage = stage + wid * 16 * 20;
    const int srow = lane >> 1;         // 0..15
    const int shalf = (lane & 1) * 8;   // 0 / 8
    #pragma unroll
    for (int mi = 0; mi < 2; mi++) {
        #pragma unroll
        for (int ni = 0; ni < 4; ni++) {
            wmma::store_matrix_sync(my_stage, c[mi][ni], 20, wmma::mem_row_major);
            __syncwarp();
            int gr = row0 + wm * 32 + mi * 16 + srow;
            if (gr < N) {
                float di = dinv[gr];
                float4 v0 = *(float4*)(my_stage + srow * 20 + shalf);
                float4 v1 = *(float4*)(my_stage + srow * 20 + shalf + 4);
                v0.x *= di; v0.y *= di; v0.z *= di; v0.w *= di;
                v1.x *= di; v1.y *= di; v1.z *= di; v1.w *= di;
                float* dst = ts + (size_t)gr * ldts + coloff + wn * 64 + ni * 16 + shalf;
                *(float4*)dst = v0;
                // careful: v1 is shalf+4 within the same 8-col half
                *(float4*)(dst + 4) = v1;
            }
            __syncwarp();
        }
    }
}

// ---------------------------------------------------------------------------
// Gather-aggregation, 128 wide (layer 1): warp per node.
//   h[d] = relu( dinv[d]*(ts[d] + sum_{s in adj(d)} ts[s]) + b )
// ---------------------------------------------------------------------------
__global__ __launch_bounds__(256)
void k_agg128(const float* __restrict__ ts, const int* __restrict__ adj,
              const int* __restrict__ base, const int* __restrict__ deg,
              const float* __restrict__ dinv, const float* __restrict__ b,
              float* __restrict__ h, int N)
{
    int node = (blockIdx.x * blockDim.x + threadIdx.x) >> 5;
    int lane = threadIdx.x & 31;
    if (node >= N) return;

    float4 acc = __ldg((const float4*)(ts + (size_t)node * 128) + lane);
    int e0 = base[node], cnt = deg[node];

    for (int eb = 0; eb < cnt; eb += 32) {
        int rem = cnt - eb;
        int myidx = (lane < rem) ? __ldg(&adj[e0 + eb + lane]) : 0;
        int m = rem < 32 ? rem : 32;
        for (int j = 0; j < m; j++) {
            int s = __shfl_sync(0xffffffffu, myidx, j);
            float4 v = __ldg((const float4*)(ts + (size_t)s * 128) + lane);
            acc.x += v.x; acc.y += v.y; acc.z += v.z; acc.w += v.w;
        }
    }

    float di = dinv[node];
    float4 bb = __ldg((const float4*)b + lane);
    float4 o;
    o.x = fmaxf(fmaf(acc.x, di, bb.x), 0.f);
    o.y = fmaxf(fmaf(acc.y, di, bb.y), 0.f);
    o.z = fmaxf(fmaf(acc.z, di, bb.z), 0.f);
    o.w = fmaxf(fmaf(acc.w, di, bb.w), 0.f);
    ((float4*)(h + (size_t)node * 128))[lane] = o;
}

// ---------------------------------------------------------------------------
// Gather-aggregation, 256 wide (mu || logstd): warp per node, 8 floats/lane.
// ---------------------------------------------------------------------------
__global__ __launch_bounds__(256)
void k_agg256(const float* __restrict__ ts2, const int* __restrict__ adj,
              const int* __restrict__ base, const int* __restrict__ deg,
              const float* __restrict__ dinv,
              const float* __restrict__ bmu, const float* __restrict__ bls,
              float* __restrict__ mu, float* __restrict__ ls, int N)
{
    int node = (blockIdx.x * blockDim.x + threadIdx.x) >> 5;
    int lane = threadIdx.x & 31;
    if (node >= N) return;

    const float4* self = (const float4*)(ts2 + (size_t)node * 256);
    float4 am = __ldg(self + lane);
    float4 al = __ldg(self + 32 + lane);
    int e0 = base[node], cnt = deg[node];

    for (int eb = 0; eb < cnt; eb += 32) {
        int rem = cnt - eb;
        int myidx = (lane < rem) ? __ldg(&adj[e0 + eb + lane]) : 0;
        int m = rem < 32 ? rem : 32;
        for (int j = 0; j < m; j++) {
            int s = __shfl_sync(0xffffffffu, myidx, j);
            const float4* row = (const float4*)(ts2 + (size_t)s * 256);
            float4 vm = __ldg(row + lane);
            float4 vl = __ldg(row + 32 + lane);
            am.x += vm.x; am.y += vm.y; am.z += vm.z; am.w += vm.w;
            al.x += vl.x; al.y += vl.y; al.z += vl.z; al.w += vl.w;
        }
    }

    float di = dinv[node];
    float4 bm = __ldg((const float4*)bmu + lane);
    float4 bl = __ldg((const float4*)bls + lane);
    float4 om, ol;
    om.x = fmaf(am.x, di, bm.x); om.y = fmaf(am.y, di, bm.y);
    om.z = fmaf(am.z, di, bm.z); om.w = fmaf(am.w, di, bm.w);
    ol.x = fmaf(al.x, di, bl.x); ol.y = fmaf(al.y, di, bl.y);
    ol.z = fmaf(al.z, di, bl.z); ol.w = fmaf(al.w, di, bl.w);
    ((float4*)(mu + (size_t)node * 128))[lane] = om;
    ((float4*)(ls + (size_t)node * 128))[lane] = ol;
}

// ---------------------------------------------------------------------------

extern "C" void kernel_launch(void* const* d_in, const int* in_sizes, int n_in,
                              void* d_out, int out_size)
{
    const float* x   = (const float*)d_in[0];
    const int*   ei  = (const int*)  d_in[1];
    const float* W1  = (const float*)d_in[2];
    const float* b1  = (const float*)d_in[3];
    const float* Wmu = (const float*)d_in[4];
    const float* bmu = (const float*)d_in[5];
    const float* Wls = (const float*)d_in[6];
    const float* bls = (const float*)d_in[7];

    const int N = in_sizes[0] / 256;   // C_in = 256
    const int E = in_sizes[1] / 2;
    const int* src = ei;
    const int* dst = ei + E;

    float* out = (float*)d_out;
    float* mu  = out;
    float* ls  = out + (size_t)N * HDIM;

    int *deg, *base, *cursor, *part, *adj;
    float *dinv, *ts1, *h, *ts2;
    __nv_bfloat16 *ah, *al, *wh, *wl;
    cudaGetSymbolAddress((void**)&deg,    g_deg);
    cudaGetSymbolAddress((void**)&base,   g_base);
    cudaGetSymbolAddress((void**)&cursor, g_cursor);
    cudaGetSymbolAddress((void**)&part,   g_part);
    cudaGetSymbolAddress((void**)&adj,    g_adj);
    cudaGetSymbolAddress((void**)&dinv,   g_dinv);
    cudaGetSymbolAddress((void**)&ts1,    g_ts1);
    cudaGetSymbolAddress((void**)&h,      g_h);
    cudaGetSymbolAddress((void**)&ts2,    g_ts2);
    cudaGetSymbolAddress((void**)&ah,     g_ah);
    cudaGetSymbolAddress((void**)&al,     g_al);
    cudaGetSymbolAddress((void**)&wh,     g_wh);
    cudaGetSymbolAddress((void**)&wl,     g_wl);

    const int nb   = (N + 255) / 256;
    const int eb   = (E + 255) / 256;
    const int gb   = (N + 127) / 128;
    const int sbnk = (N + SCAN_B - 1) / SCAN_B;
    const int ab   = (N * 32 + 255) / 256;

    // degree + dinv + CSR (reused by all 3 aggregations)
    k_zero_int<<<nb, 256>>>(deg, N);
    k_count   <<<eb, 256>>>(dst, deg, E);
    k_dinv    <<<nb, 256>>>(deg, dinv, N);
    k_scan_block<<<sbnk, SCAN_B>>>(deg, base, part, N);
    k_scan_part <<<1, 32>>>(part, sbnk);
    k_scan_add  <<<sbnk, SCAN_B>>>(base, cursor, part, N);
    k_fill      <<<eb, 256>>>(src, dst, cursor, adj, E);

    // pre-split weights (hi/lo bf16): W1 @0, Wmu @256*128, Wls @384*128
    k_split<<<(256 * 128 / 4 + 255) / 256, 256>>>(W1,  wh,             wl,             256 * 128 / 4);
    k_split<<<(128 * 128 / 4 + 255) / 256, 256>>>(Wmu, wh + 256 * 128, wl + 256 * 128, 128 * 128 / 4);
    k_split<<<(128 * 128 / 4 + 255) / 256, 256>>>(Wls, wh + 384 * 128, wl + 384 * 128, 128 * 128 / 4);

    // layer 1: split x, GEMM, aggregate
    {
        int n4 = N * 256 / 4;
        k_split<<<(n4 + 255) / 256, 256>>>(x, ah, al, n4);
    }
    k_gemm_bf16<<<dim3(gb, 1), 256>>>(ah, al, wh, wl, wh, wl, dinv, ts1, N, 256, 128);
    k_agg128   <<<ab, 256>>>(ts1, adj, base, deg, dinv, b1, h, N);

    // layer 2: split h, merged two-head GEMM, merged aggregation
    {
        int n4 = N * 128 / 4;
        k_split<<<(n4 + 255) / 256, 256>>>(h, ah, al, n4);
    }
    k_gemm_bf16<<<dim3(gb, 2), 256>>>(ah, al,
                                      wh + 256 * 128, wl + 256 * 128,
                                      wh + 384 * 128, wl + 384 * 128,
                                      dinv, ts2, N, 128, 256);
    k_agg256   <<<ab, 256>>>(ts2, adj, base, deg, dinv, bmu, bls, mu, ls, N);
}

// round 9
// speedup vs baseline: 2.6952x; 1.1517x over previous
#include <cuda_runtime.h>
#include <cuda_bf16.h>
#include <mma.h>
#include <cstdint>

using namespace nvcuda;

// ---------------------------------------------------------------------------
// Stochastic_encoder (VGAE GCN encoder), bf16 split-precision wmma GEMMs.
// Layer 2 uses agg-before-GEMM (agg and W multiply commute):
//   ts1  = (x@W1)*dinv[row]                       (GEMM, dinv epilogue)
//   hsc  = dinv*relu(dinv*(ts1[self]+sum ts1)+b1) (gather agg)
//   hagg = dinv*(hsc[self] + sum hsc)  -> bf16 hi/lo directly
//   mu   = hagg@Wmu + bmu ; ls = hagg@Wls + bls   (GEMM, bias epilogue -> out)
// ---------------------------------------------------------------------------

#define NMAX   50176
#define EMAX   800000
#define HDIM   128
#define SCAN_B 1024

__device__ int   g_deg   [NMAX];
__device__ int   g_base  [NMAX];
__device__ int   g_cursor[NMAX];
__device__ int   g_part  [256];
__device__ int   g_adj   [EMAX];
__device__ float g_dinv  [NMAX];
__device__ float g_ts1   [(size_t)NMAX * HDIM];
__device__ float g_hsc   [(size_t)NMAX * HDIM];

__device__ __nv_bfloat16 g_ah[(size_t)NMAX * 256];
__device__ __nv_bfloat16 g_al[(size_t)NMAX * 256];
__device__ __nv_bfloat16 g_wh[512 * 128];   // W1 @0 (256 rows), Wmu @256, Wls @384
__device__ __nv_bfloat16 g_wl[512 * 128];

// ---------------------------------------------------------------------------

__global__ void k_zero_int(int* __restrict__ p, int n) {
    int i = blockIdx.x * blockDim.x + threadIdx.x;
    if (i < n) p[i] = 0;
}

__global__ void k_count(const int* __restrict__ dst, int* __restrict__ deg, int E) {
    int i = blockIdx.x * blockDim.x + threadIdx.x;
    if (i < E) atomicAdd(&deg[dst[i]], 1);
}

__global__ void k_dinv(const int* __restrict__ deg, float* __restrict__ dinv, int n) {
    int i = blockIdx.x * blockDim.x + threadIdx.x;
    if (i < n) dinv[i] = rsqrtf((float)deg[i] + 1.0f);
}

// --- 3-kernel exclusive scan of deg -> base (cursor = base copy) ----------
__global__ void k_scan_block(const int* __restrict__ deg, int* __restrict__ base,
                             int* __restrict__ part, int n)
{
    __shared__ int sh[SCAN_B];
    int gi = blockIdx.x * SCAN_B + threadIdx.x;
    int v = (gi < n) ? deg[gi] : 0;
    sh[threadIdx.x] = v;
    __syncthreads();
    #pragma unroll
    for (int off = 1; off < SCAN_B; off <<= 1) {
        int t = (threadIdx.x >= off) ? sh[threadIdx.x - off] : 0;
        __syncthreads();
        sh[threadIdx.x] += t;
        __syncthreads();
    }
    if (gi < n) base[gi] = sh[threadIdx.x] - v;
    if (threadIdx.x == SCAN_B - 1) part[blockIdx.x] = sh[threadIdx.x];
}

__global__ void k_scan_part(int* __restrict__ part, int nb) {
    if (threadIdx.x == 0) {
        int acc = 0;
        for (int i = 0; i < nb; i++) { int v = part[i]; part[i] = acc; acc += v; }
    }
}

__global__ void k_scan_add(int* __restrict__ base, int* __restrict__ cursor,
                           const int* __restrict__ part, int n) {
    int gi = blockIdx.x * SCAN_B + threadIdx.x;
    if (gi < n) {
        int b = base[gi] + part[blockIdx.x];
        base[gi]   = b;
        cursor[gi] = b;
    }
}

__global__ void k_fill(const int* __restrict__ src, const int* __restrict__ dst,
                       int* __restrict__ cursor, int* __restrict__ adj, int E)
{
    int i = blockIdx.x * blockDim.x + threadIdx.x;
    if (i < E) {
        int pos = atomicAdd(&cursor[dst[i]], 1);
        adj[pos] = src[i];
    }
}

// ---------------------------------------------------------------------------
// fp32 -> bf16 (hi, lo) split: hi = bf16(v), lo = bf16(v - hi). Vectorized x4.
// ---------------------------------------------------------------------------
__global__ void k_split(const float* __restrict__ src,
                        __nv_bfloat16* __restrict__ hi,
                        __nv_bfloat16* __restrict__ lo, int n4)
{
    int i = blockIdx.x * blockDim.x + threadIdx.x;
    if (i >= n4) return;
    float4 v = ((const float4*)src)[i];
    __nv_bfloat16 hx = __float2bfloat16(v.x);
    __nv_bfloat16 hy = __float2bfloat16(v.y);
    __nv_bfloat16 hz = __float2bfloat16(v.z);
    __nv_bfloat16 hw = __float2bfloat16(v.w);
    __nv_bfloat162* hp = (__nv_bfloat162*)hi;
    __nv_bfloat162* lp = (__nv_bfloat162*)lo;
    hp[2 * i]     = __nv_bfloat162(hx, hy);
    hp[2 * i + 1] = __nv_bfloat162(hz, hw);
    lp[2 * i]     = __nv_bfloat162(__float2bfloat16(v.x - __bfloat162float(hx)),
                                   __float2bfloat16(v.y - __bfloat162float(hy)));
    lp[2 * i + 1] = __nv_bfloat162(__float2bfloat16(v.z - __bfloat162float(hz)),
                                   __float2bfloat16(v.w - __bfloat162float(hw)));
}

// ---------------------------------------------------------------------------
// bf16 split-precision wmma GEMM (C = Ah*Wh + Al*Wh + Ah*Wl, fp32 accum).
// BM=128, BN=128, BK=32, 8 warps (4x2), fragments m16n16k16.
// mode 0: out[r,c] = C[r,c]*dinv[r]       (out/ W selected by blockIdx.y)
// mode 1: out[r,c] = C[r,c] + bias[c]
// ---------------------------------------------------------------------------
#define A_PITCH 40
#define B_PITCH 136

__global__ __launch_bounds__(256, 2)
void k_gemm_bf16(const __nv_bfloat16* __restrict__ Ah,
                 const __nv_bfloat16* __restrict__ Al,
                 const __nv_bfloat16* __restrict__ Wh_a,
                 const __nv_bfloat16* __restrict__ Wl_a,
                 const __nv_bfloat16* __restrict__ Wh_b,
                 const __nv_bfloat16* __restrict__ Wl_b,
                 const float* __restrict__ dinv,
                 const float* __restrict__ bias_a,
                 const float* __restrict__ bias_b,
                 float* __restrict__ out_a, float* __restrict__ out_b,
                 int N, int K, int ldts, int coloff_mult, int mode)
{
    __shared__ __align__(32) unsigned char smem_raw[
        128 * A_PITCH * 2 * 2 + 32 * B_PITCH * 2 * 2];
    __nv_bfloat16* Ah_s = (__nv_bfloat16*)smem_raw;
    __nv_bfloat16* Al_s = Ah_s + 128 * A_PITCH;
    __nv_bfloat16* Bh_s = Al_s + 128 * A_PITCH;
    __nv_bfloat16* Bl_s = Bh_s + 32 * B_PITCH;
    float*         stage = (float*)smem_raw;   // reused in epilogue

    const __nv_bfloat16* Wh = blockIdx.y ? Wh_b : Wh_a;
    const __nv_bfloat16* Wl = blockIdx.y ? Wl_b : Wl_a;
    const float* bias = blockIdx.y ? bias_b : bias_a;
    float* outp = blockIdx.y ? out_b : out_a;
    const int coloff = blockIdx.y * coloff_mult;

    const int tid  = threadIdx.x;
    const int wid  = tid >> 5;
    const int lane = tid & 31;
    const int wm   = wid >> 1;
    const int wn   = wid & 1;
    const int row0 = blockIdx.x * 128;

    const int ar  = tid >> 1;
    const int ac  = (tid & 1) * 16;
    const int br  = tid >> 3;
    const int bc  = (tid & 7) * 16;

    wmma::fragment<wmma::accumulator, 16, 16, 16, float> c[2][4];
    #pragma unroll
    for (int mi = 0; mi < 2; mi++)
        #pragma unroll
        for (int ni = 0; ni < 4; ni++)
            wmma::fill_fragment(c[mi][ni], 0.0f);

    for (int k0 = 0; k0 < K; k0 += 32) {
        {
            const uint4* gh = (const uint4*)(Ah + (size_t)(row0 + ar) * K + k0 + ac);
            const uint4* gl = (const uint4*)(Al + (size_t)(row0 + ar) * K + k0 + ac);
            uint4* sh = (uint4*)(Ah_s + ar * A_PITCH + ac);
            uint4* sl = (uint4*)(Al_s + ar * A_PITCH + ac);
            sh[0] = gh[0]; sh[1] = gh[1];
            sl[0] = gl[0]; sl[1] = gl[1];
        }
        {
            const uint4* gh = (const uint4*)(Wh + (size_t)(k0 + br) * 128 + bc);
            const uint4* gl = (const uint4*)(Wl + (size_t)(k0 + br) * 128 + bc);
            uint4* sh = (uint4*)(Bh_s + br * B_PITCH + bc);
            uint4* sl = (uint4*)(Bl_s + br * B_PITCH + bc);
            sh[0] = gh[0]; sh[1] = gh[1];
            sl[0] = gl[0]; sl[1] = gl[1];
        }
        __syncthreads();

        #pragma unroll
        for (int kk = 0; kk < 32; kk += 16) {
            wmma::fragment<wmma::matrix_a, 16, 16, 16, __nv_bfloat16,
                           wmma::row_major> fah[2], fal[2];
            #pragma unroll
            for (int mi = 0; mi < 2; mi++) {
                wmma::load_matrix_sync(fah[mi],
                    Ah_s + (wm * 32 + mi * 16) * A_PITCH + kk, A_PITCH);
                wmma::load_matrix_sync(fal[mi],
                    Al_s + (wm * 32 + mi * 16) * A_PITCH + kk, A_PITCH);
            }
            #pragma unroll
            for (int ni = 0; ni < 4; ni++) {
                wmma::fragment<wmma::matrix_b, 16, 16, 16, __nv_bfloat16,
                               wmma::row_major> fbh, fbl;
                wmma::load_matrix_sync(fbh,
                    Bh_s + kk * B_PITCH + wn * 64 + ni * 16, B_PITCH);
                wmma::load_matrix_sync(fbl,
                    Bl_s + kk * B_PITCH + wn * 64 + ni * 16, B_PITCH);
                #pragma unroll
                for (int mi = 0; mi < 2; mi++) {
                    wmma::mma_sync(c[mi][ni], fah[mi], fbh, c[mi][ni]);
                    wmma::mma_sync(c[mi][ni], fal[mi], fbh, c[mi][ni]);
                    wmma::mma_sync(c[mi][ni], fah[mi], fbl, c[mi][ni]);
                }
            }
        }
        __syncthreads();
    }

    // epilogue: stage through smem, apply dinv (mode 0) or bias (mode 1)
    float* my_stage = stage + wid * 16 * 20;
    const int srow  = lane >> 1;
    const int shalf = (lane & 1) * 8;
    #pragma unroll
    for (int mi = 0; mi < 2; mi++) {
        #pragma unroll
        for (int ni = 0; ni < 4; ni++) {
            wmma::store_matrix_sync(my_stage, c[mi][ni], 20, wmma::mem_row_major);
            __syncwarp();
            int gr = row0 + wm * 32 + mi * 16 + srow;
            if (gr < N) {
                int ccol = coloff + wn * 64 + ni * 16 + shalf;
                float4 v0 = *(float4*)(my_stage + srow * 20 + shalf);
                float4 v1 = *(float4*)(my_stage + srow * 20 + shalf + 4);
                if (mode == 0) {
                    float di = dinv[gr];
                    v0.x *= di; v0.y *= di; v0.z *= di; v0.w *= di;
                    v1.x *= di; v1.y *= di; v1.z *= di; v1.w *= di;
                } else {
                    int bcol = wn * 64 + ni * 16 + shalf;
                    float4 b0 = *(const float4*)(bias + bcol);
                    float4 b1 = *(const float4*)(bias + bcol + 4);
                    v0.x += b0.x; v0.y += b0.y; v0.z += b0.z; v0.w += b0.w;
                    v1.x += b1.x; v1.y += b1.y; v1.z += b1.z; v1.w += b1.w;
                }
                float* dst = outp + (size_t)gr * ldts + ccol;
                *(float4*)dst       = v0;
                *(float4*)(dst + 4) = v1;
            }
            __syncwarp();
        }
    }
}

// ---------------------------------------------------------------------------
// Layer-1 aggregation (warp per node):
//   o   = relu( dinv[d]*(ts1[d] + sum_{s in adj(d)} ts1[s]) + b1 )
//   hsc = dinv[d] * o                       (only hsc is needed downstream)
// ---------------------------------------------------------------------------
__global__ __launch_bounds__(256)
void k_agg1(const float* __restrict__ ts, const int* __restrict__ adj,
            const int* __restrict__ base, const int* __restrict__ deg,
            const float* __restrict__ dinv, const float* __restrict__ b,
            float* __restrict__ hsc, int N)
{
    int node = (blockIdx.x * blockDim.x + threadIdx.x) >> 5;
    int lane = threadIdx.x & 31;
    if (node >= N) return;

    float4 acc = __ldg((const float4*)(ts + (size_t)node * 128) + lane);
    int e0 = base[node], cnt = deg[node];

    for (int eb = 0; eb < cnt; eb += 32) {
        int rem = cnt - eb;
        int myidx = (lane < rem) ? __ldg(&adj[e0 + eb + lane]) : 0;
        int m = rem < 32 ? rem : 32;
        for (int j = 0; j < m; j++) {
            int s = __shfl_sync(0xffffffffu, myidx, j);
            float4 v = __ldg((const float4*)(ts + (size_t)s * 128) + lane);
            acc.x += v.x; acc.y += v.y; acc.z += v.z; acc.w += v.w;
        }
    }

    float di = dinv[node];
    float4 bb = __ldg((const float4*)b + lane);
    float4 o;
    o.x = di * fmaxf(fmaf(acc.x, di, bb.x), 0.f);
    o.y = di * fmaxf(fmaf(acc.y, di, bb.y), 0.f);
    o.z = di * fmaxf(fmaf(acc.z, di, bb.z), 0.f);
    o.w = di * fmaxf(fmaf(acc.w, di, bb.w), 0.f);
    ((float4*)(hsc + (size_t)node * 128))[lane] = o;
}

// ---------------------------------------------------------------------------
// Layer-2 pre-GEMM aggregation (warp per node):
//   hagg = dinv[d]*( hsc[d] + sum_{s in adj(d)} hsc[s] )
// Emits bf16 hi/lo split directly (GEMM A operand), no fp32 intermediate.
// ---------------------------------------------------------------------------
__global__ __launch_bounds__(256)
void k_agg2(const float* __restrict__ hsc, const int* __restrict__ adj,
            const int* __restrict__ base, const int* __restrict__ deg,
            const float* __restrict__ dinv,
            __nv_bfloat16* __restrict__ ah, __nv_bfloat16* __restrict__ al,
            int N)
{
    int node = (blockIdx.x * blockDim.x + threadIdx.x) >> 5;
    int lane = threadIdx.x & 31;
    if (node >= N) return;

    float4 acc = __ldg((const float4*)(hsc + (size_t)node * 128) + lane);
    int e0 = base[node], cnt = deg[node];

    for (int eb = 0; eb < cnt; eb += 32) {
        int rem = cnt - eb;
        int myidx = (lane < rem) ? __ldg(&adj[e0 + eb + lane]) : 0;
        int m = rem < 32 ? rem : 32;
        for (int j = 0; j < m; j++) {
            int s = __shfl_sync(0xffffffffu, myidx, j);
            float4 v = __ldg((const float4*)(hsc + (size_t)s * 128) + lane);
            acc.x += v.x; acc.y += v.y; acc.z += v.z; acc.w += v.w;
        }
    }

    float di = dinv[node];
    acc.x *= di; acc.y *= di; acc.z *= di; acc.w *= di;

    __nv_bfloat16 hx = __float2bfloat16(acc.x);
    __nv_bfloat16 hy = __float2bfloat16(acc.y);
    __nv_bfloat16 hz = __float2bfloat16(acc.z);
    __nv_bfloat16 hw = __float2bfloat16(acc.w);
    __nv_bfloat162* hp = (__nv_bfloat162*)(ah + (size_t)node * 128) + lane * 2;
    __nv_bfloat162* lp = (__nv_bfloat162*)(al + (size_t)node * 128) + lane * 2;
    hp[0] = __nv_bfloat162(hx, hy);
    hp[1] = __nv_bfloat162(hz, hw);
    lp[0] = __nv_bfloat162(__float2bfloat16(acc.x - __bfloat162float(hx)),
                           __float2bfloat16(acc.y - __bfloat162float(hy)));
    lp[1] = __nv_bfloat162(__float2bfloat16(acc.z - __bfloat162float(hz)),
                           __float2bfloat16(acc.w - __bfloat162float(hw)));
}

// ---------------------------------------------------------------------------

extern "C" void kernel_launch(void* const* d_in, const int* in_sizes, int n_in,
                              void* d_out, int out_size)
{
    const float* x   = (const float*)d_in[0];
    const int*   ei  = (const int*)  d_in[1];
    const float* W1  = (const float*)d_in[2];
    const float* b1  = (const float*)d_in[3];
    const float* Wmu = (const float*)d_in[4];
    const float* bmu = (const float*)d_in[5];
    const float* Wls = (const float*)d_in[6];
    const float* bls = (const float*)d_in[7];

    const int N = in_sizes[0] / 256;   // C_in = 256
    const int E = in_sizes[1] / 2;
    const int* src = ei;
    const int* dst = ei + E;

    float* out = (float*)d_out;
    float* mu  = out;
    float* ls  = out + (size_t)N * HDIM;

    int *deg, *base, *cursor, *part, *adj;
    float *dinv, *ts1, *hsc;
    __nv_bfloat16 *ah, *al, *wh, *wl;
    cudaGetSymbolAddress((void**)&deg,    g_deg);
    cudaGetSymbolAddress((void**)&base,   g_base);
    cudaGetSymbolAddress((void**)&cursor, g_cursor);
    cudaGetSymbolAddress((void**)&part,   g_part);
    cudaGetSymbolAddress((void**)&adj,    g_adj);
    cudaGetSymbolAddress((void**)&dinv,   g_dinv);
    cudaGetSymbolAddress((void**)&ts1,    g_ts1);
    cudaGetSymbolAddress((void**)&hsc,    g_hsc);
    cudaGetSymbolAddress((void**)&ah,     g_ah);
    cudaGetSymbolAddress((void**)&al,     g_al);
    cudaGetSymbolAddress((void**)&wh,     g_wh);
    cudaGetSymbolAddress((void**)&wl,     g_wl);

    const int nb   = (N + 255) / 256;
    const int eb   = (E + 255) / 256;
    const int gb   = (N + 127) / 128;
    const int sbnk = (N + SCAN_B - 1) / SCAN_B;
    const int ab   = (N * 32 + 255) / 256;

    // degree + dinv + CSR
    k_zero_int<<<nb, 256>>>(deg, N);
    k_count   <<<eb, 256>>>(dst, deg, E);
    k_dinv    <<<nb, 256>>>(deg, dinv, N);
    k_scan_block<<<sbnk, SCAN_B>>>(deg, base, part, N);
    k_scan_part <<<1, 32>>>(part, sbnk);
    k_scan_add  <<<sbnk, SCAN_B>>>(base, cursor, part, N);
    k_fill      <<<eb, 256>>>(src, dst, cursor, adj, E);

    // pre-split weights: W1 @0, Wmu @256*128, Wls @384*128
    k_split<<<(256 * 128 / 4 + 255) / 256, 256>>>(W1,  wh,             wl,             256 * 128 / 4);
    k_split<<<(128 * 128 / 4 + 255) / 256, 256>>>(Wmu, wh + 256 * 128, wl + 256 * 128, 128 * 128 / 4);
    k_split<<<(128 * 128 / 4 + 255) / 256, 256>>>(Wls, wh + 384 * 128, wl + 384 * 128, 128 * 128 / 4);

    // layer 1: split x; ts1 = (x@W1)*dinv; hsc = dinv*relu(agg(ts1)+b1)
    {
        int n4 = N * 256 / 4;
        k_split<<<(n4 + 255) / 256, 256>>>(x, ah, al, n4);
    }
    k_gemm_bf16<<<dim3(gb, 1), 256>>>(ah, al, wh, wl, wh, wl,
                                      dinv, nullptr, nullptr,
                                      ts1, ts1, N, 256, 128, 0, 0);
    k_agg1<<<ab, 256>>>(ts1, adj, base, deg, dinv, b1, hsc, N);

    // layer 2: aggregate first (bf16 split output), then two bias-GEMMs -> out
    k_agg2<<<ab, 256>>>(hsc, adj, base, deg, dinv, ah, al, N);
    k_gemm_bf16<<<dim3(gb, 2), 256>>>(ah, al,
                                      wh + 256 * 128, wl + 256 * 128,
                                      wh + 384 * 128, wl + 384 * 128,
                                      dinv, bmu, bls,
                                      mu, ls, N, 128, 128, 0, 1);
}